// round 11
// baseline (speedup 1.0000x reference)
#include <cuda_runtime.h>
#include <cuda_bf16.h>
#include <cstdint>

#define D      128
#define NROW   50000
#define NCOL   50000
#define NTOT   (NROW + NCOL)
#define BM     64

// X tile: 64 rows x 128 k bf16, row stride 272B
#define LDB_B   272
#define XTILE_B (64 * LDB_B)          // 17408
// W half-tile: 128 n-rows x 64 k bf16, row stride 144B
#define LDW_B   144
#define WHALF_B (128 * LDW_B)         // 18432
#define WHALF_U4 (WHALF_B / 16)       // 1152

// Scratch (alloc-free rule: __device__ globals)
__device__ float g_hrow[(size_t)NROW * D];
__device__ uint4 g_wt[4][2][2][WHALF_U4];   // [matrix][khalf][hi/lo]
__device__ int   g_cnt[NTOT];
__device__ int   g_ptr[NTOT + 1];
__device__ int   g_cur[NTOT];
__device__ int   g_bsum[128];
__device__ int2  g_edges[1200000];

__device__ __forceinline__ float leaky(float v) { return v >= 0.f ? v : 0.01f * v; }

// ---------------- CSR build ----------------
__global__ void zero_cnt_kernel(int* __restrict__ cnt, int n) {
    int i = blockIdx.x * blockDim.x + threadIdx.x;
    if (i < n) cnt[i] = 0;
}

__global__ void hist2_kernel(const int* __restrict__ dst1, const int* __restrict__ dst2,
                             int* __restrict__ cnt, int E) {
    int e = blockIdx.x * blockDim.x + threadIdx.x;
    if (e >= 2 * E) return;
    if (e < E) atomicAdd(cnt + __ldg(dst1 + e), 1);
    else       atomicAdd(cnt + NROW + __ldg(dst2 + e - E), 1);
}

__global__ void scan_blk_kernel(const int* __restrict__ cnt, int* __restrict__ ptr,
                                int* __restrict__ bsum, int n) {
    __shared__ int wsum[32];
    int tid = threadIdx.x, lane = tid & 31, wid = tid >> 5;
    int i = blockIdx.x * 1024 + tid;
    int x = (i < n) ? cnt[i] : 0;
    int v = x;
    #pragma unroll
    for (int o = 1; o < 32; o <<= 1) { int t = __shfl_up_sync(~0u, v, o); if (lane >= o) v += t; }
    if (lane == 31) wsum[wid] = v;
    __syncthreads();
    if (wid == 0) {
        int s = wsum[lane];
        #pragma unroll
        for (int o = 1; o < 32; o <<= 1) { int t = __shfl_up_sync(~0u, s, o); if (lane >= o) s += t; }
        wsum[lane] = s;
    }
    __syncthreads();
    int woff = wid ? wsum[wid - 1] : 0;
    if (i < n) ptr[i] = woff + v - x;
    if (tid == 1023) bsum[blockIdx.x] = wsum[31];
}

__global__ void scan_tot_kernel(int* __restrict__ bsum, int nb) {
    __shared__ int tmp[128];
    int tid = threadIdx.x;
    int x = (tid < nb) ? bsum[tid] : 0;
    tmp[tid] = x;
    __syncthreads();
    for (int o = 1; o < 128; o <<= 1) {
        int t = (tid >= o) ? tmp[tid - o] : 0;
        __syncthreads();
        tmp[tid] += t;
        __syncthreads();
    }
    if (tid < nb) bsum[tid] = tmp[tid] - x;
}

__global__ void scan_add_kernel(int* __restrict__ ptr, int* __restrict__ cur,
                                const int* __restrict__ bsum, int n, int total) {
    int i = blockIdx.x * blockDim.x + threadIdx.x;
    if (i < n) {
        int v = ptr[i] + bsum[i >> 10];
        ptr[i] = v;
        cur[i] = v;
    }
    if (i == 0) ptr[n] = total;
}

__global__ void scatter2_kernel(const int* __restrict__ src1, const int* __restrict__ dst1,
                                const float* __restrict__ w1,
                                const int* __restrict__ src2, const int* __restrict__ dst2,
                                const float* __restrict__ w2,
                                int* __restrict__ cur, int2* __restrict__ edges, int E) {
    int e = blockIdx.x * blockDim.x + threadIdx.x;
    if (e >= 2 * E) return;
    if (e < E) {
        int pos = atomicAdd(cur + __ldg(dst1 + e), 1);
        edges[pos] = make_int2(__ldg(src1 + e), __float_as_int(__ldg(w1 + e)));
    } else {
        int ee = e - E;
        int pos = atomicAdd(cur + NROW + __ldg(dst2 + ee), 1);
        edges[pos] = make_int2(__ldg(src2 + ee), __float_as_int(__ldg(w2 + ee)));
    }
}

// ---------------- weight pre-split ----------------
static __device__ __forceinline__ void split8(const float* x, uint32_t* hi, uint32_t* lo) {
    #pragma unroll
    for (int j = 0; j < 4; j++) {
        __nv_bfloat16 h0 = __float2bfloat16(x[2*j]);
        __nv_bfloat16 h1 = __float2bfloat16(x[2*j+1]);
        __nv_bfloat16 l0 = __float2bfloat16(x[2*j]   - __bfloat162float(h0));
        __nv_bfloat16 l1 = __float2bfloat16(x[2*j+1] - __bfloat162float(h1));
        hi[j] = (uint32_t)__bfloat16_as_ushort(h0) | ((uint32_t)__bfloat16_as_ushort(h1) << 16);
        lo[j] = (uint32_t)__bfloat16_as_ushort(l0) | ((uint32_t)__bfloat16_as_ushort(l1) << 16);
    }
}

static __device__ __forceinline__ void split2(float x0, float x1, uint32_t& hi, uint32_t& lo) {
    __nv_bfloat16 h0 = __float2bfloat16(x0);
    __nv_bfloat16 h1 = __float2bfloat16(x1);
    __nv_bfloat16 l0 = __float2bfloat16(x0 - __bfloat162float(h0));
    __nv_bfloat16 l1 = __float2bfloat16(x1 - __bfloat162float(h1));
    hi = (uint32_t)__bfloat16_as_ushort(h0) | ((uint32_t)__bfloat16_as_ushort(h1) << 16);
    lo = (uint32_t)__bfloat16_as_ushort(l0) | ((uint32_t)__bfloat16_as_ushort(l1) << 16);
}

__global__ void split_w_kernel(const float* __restrict__ Wa, const float* __restrict__ Wb,
                               const float* __restrict__ Wc, const float* __restrict__ Wd) {
    int task = blockIdx.x * blockDim.x + threadIdx.x;   // 0..8191
    int m = task >> 11;
    int tt = task & 2047;
    int n = tt & 127, kg = tt >> 7;
    const float* W = (m == 0) ? Wa : (m == 1) ? Wb : (m == 2) ? Wc : Wd;
    float v[8];
    #pragma unroll
    for (int j = 0; j < 8; j++) v[j] = __ldg(W + (kg * 8 + j) * D + n);
    uint32_t hi[4], lo[4];
    split8(v, hi, lo);
    int half = kg >> 3, kgl = kg & 7;
    int idx = n * 9 + kgl;
    g_wt[m][half][0][idx] = make_uint4(hi[0], hi[1], hi[2], hi[3]);
    g_wt[m][half][1][idx] = make_uint4(lo[0], lo[1], lo[2], lo[3]);
}

// ---------------- fused gather + HMMA MLP ----------------
#define SM_XHI  0
#define SM_XLO  (SM_XHI + XTILE_B)
#define SM_WS0  (SM_XLO + XTILE_B)
#define SM_WS1  (SM_WS0 + WHALF_B)
#define SM_WS2  (SM_WS1 + WHALF_B)
#define SM_WS3  (SM_WS2 + WHALF_B)
#define SM_B1   (SM_WS3 + WHALF_B)
#define SM_B2   (SM_B1 + 512)
#define SM_TOTAL (SM_B2 + 512)            // 109568 -> 2 CTAs/SM
#define SM_FST  SM_WS0
#define LDF     132

static __device__ __forceinline__ uint32_t smem_u32(const void* p) {
    uint32_t a;
    asm("{ .reg .u64 t; cvta.to.shared.u64 t, %1; cvt.u32.u64 %0, t; }" : "=r"(a) : "l"(p));
    return a;
}

static __device__ __forceinline__ void ldsm4(uint32_t* r, uint32_t addr) {
    asm volatile("ldmatrix.sync.aligned.m8n8.x4.shared.b16 {%0,%1,%2,%3}, [%4];"
                 : "=r"(r[0]), "=r"(r[1]), "=r"(r[2]), "=r"(r[3]) : "r"(addr));
}

static __device__ __forceinline__ void mma16816(float* d, const uint32_t* a,
                                                uint32_t b0, uint32_t b1) {
    asm volatile("mma.sync.aligned.m16n8k16.row.col.f32.bf16.bf16.f32 "
                 "{%0,%1,%2,%3}, {%4,%5,%6,%7}, {%8,%9}, {%0,%1,%2,%3};"
                 : "+f"(d[0]), "+f"(d[1]), "+f"(d[2]), "+f"(d[3])
                 : "r"(a[0]), "r"(a[1]), "r"(a[2]), "r"(a[3]), "r"(b0), "r"(b1));
}

static __device__ __forceinline__ void stage_whalf(uint32_t smb, uint32_t hi_off, uint32_t lo_off,
                                                   const uint4* __restrict__ half_base, int tid) {
    const uint4* hi = half_base;
    const uint4* lo = half_base + WHALF_U4;
    for (int i = tid; i < WHALF_U4; i += 256) {
        asm volatile("cp.async.cg.shared.global [%0], [%1], 16;"
                     :: "r"(smb + hi_off + (uint32_t)i * 16), "l"(hi + i));
        asm volatile("cp.async.cg.shared.global [%0], [%1], 16;"
                     :: "r"(smb + lo_off + (uint32_t)i * 16), "l"(lo + i));
    }
    asm volatile("cp.async.commit_group;" ::: "memory");
}
template <int N>
static __device__ __forceinline__ void wait_cp_n() {
    asm volatile("cp.async.wait_group %0;" :: "n"(N) : "memory");
}

static __device__ __forceinline__ void do_half(uint32_t smb, uint32_t whi, uint32_t wlo,
                                               int khalf, int m0, int wn, int lane,
                                               float acc[8][4]) {
    const int rsel = lane & 15;
    const uint32_t koff = (uint32_t)((lane >> 4) << 4);
    #pragma unroll
    for (int kk = 0; kk < 4; kk++) {
        uint32_t rowkA = (uint32_t)(khalf * 4 + kk) * 32 + koff;
        uint32_t rowkB = (uint32_t)kk * 32 + koff;
        uint32_t ahi[4], alo[4];
        ldsm4(ahi, smb + SM_XHI + (uint32_t)(m0 + rsel) * LDB_B + rowkA);
        ldsm4(alo, smb + SM_XLO + (uint32_t)(m0 + rsel) * LDB_B + rowkA);
        #pragma unroll
        for (int p = 0; p < 4; p++) {
            uint32_t boff = (uint32_t)((wn * 4 + p) * 16 + rsel) * LDW_B + rowkB;
            uint32_t bh[4], bl[4];
            ldsm4(bh, smb + whi + boff);
            ldsm4(bl, smb + wlo + boff);
            mma16816(acc[2*p],   ahi, bh[0], bh[2]);
            mma16816(acc[2*p+1], ahi, bh[1], bh[3]);
            mma16816(acc[2*p],   ahi, bl[0], bl[2]);
            mma16816(acc[2*p+1], ahi, bl[1], bl[3]);
            mma16816(acc[2*p],   alo, bh[0], bh[2]);
            mma16816(acc[2*p+1], alo, bh[1], bh[3]);
        }
    }
}

__global__ void __launch_bounds__(256, 2)
fused_kernel(const float4* __restrict__ feat_src,   // gather source (32 float4/row)
             const float* __restrict__ feat_self,   // self features of dst side
             const int* __restrict__ ptr, const int2* __restrict__ edges, int off,
             const uint4* __restrict__ wmat1, const uint4* __restrict__ wmat2,
             const float* __restrict__ b1, const float* __restrict__ b2,
             const float* __restrict__ eps_p,
             float* __restrict__ h_out, float* __restrict__ out, int N) {
    extern __shared__ char sm[];
    const uint32_t smb = smem_u32(sm);
    const int tid = threadIdx.x;
    const int wid = tid >> 5;
    const int lane = tid & 31;
    const int m0 = (wid & 3) * 16;
    const int wn = wid >> 2;
    const int row0 = blockIdx.x * BM;
    const float eps1 = 1.f + __ldg(eps_p);

    const float4* feat4 = (const float4*)feat_self;
    float* sB1 = (float*)(sm + SM_B1);
    float* sB2 = (float*)(sm + SM_B2);

    // prefetch W1 (both halves) under the gather phase
    stage_whalf(smb, SM_WS0, SM_WS1, wmat1, tid);                 // group: W1h1
    stage_whalf(smb, SM_WS2, SM_WS3, wmat1 + 2 * WHALF_U4, tid);  // group: W1h2

    if (tid < 128) {
        sB1[tid] = __ldg(b1 + tid);
        sB2[tid] = __ldg(b2 + tid);
    }

    // ---- fused gather + stage: each warp handles 8 rows ----
    #pragma unroll 1
    for (int j = 0; j < 8; j++) {
        int r = wid * 8 + j;            // block-local row
        int node = row0 + r;
        float4 a0 = make_float4(0.f, 0.f, 0.f, 0.f);
        float4 a1 = make_float4(0.f, 0.f, 0.f, 0.f);
        float4 v = make_float4(0.f, 0.f, 0.f, 0.f);
        if (node < N) {
            int beg = __ldg(ptr + off + node);
            int end = __ldg(ptr + off + node + 1);
            int i = beg;
            for (; i + 2 <= end; i += 2) {
                int2 e0 = __ldg(edges + i);
                int2 e1 = __ldg(edges + i + 1);
                float w0 = __int_as_float(e0.y), w1 = __int_as_float(e1.y);
                float4 v0 = __ldg(feat_src + (size_t)e0.x * 32 + lane);
                float4 v1 = __ldg(feat_src + (size_t)e1.x * 32 + lane);
                a0.x = fmaf(v0.x, w0, a0.x); a0.y = fmaf(v0.y, w0, a0.y);
                a0.z = fmaf(v0.z, w0, a0.z); a0.w = fmaf(v0.w, w0, a0.w);
                a1.x = fmaf(v1.x, w1, a1.x); a1.y = fmaf(v1.y, w1, a1.y);
                a1.z = fmaf(v1.z, w1, a1.z); a1.w = fmaf(v1.w, w1, a1.w);
            }
            if (i < end) {
                int2 e0 = __ldg(edges + i);
                float w0 = __int_as_float(e0.y);
                float4 v0 = __ldg(feat_src + (size_t)e0.x * 32 + lane);
                a0.x = fmaf(v0.x, w0, a0.x); a0.y = fmaf(v0.y, w0, a0.y);
                a0.z = fmaf(v0.z, w0, a0.z); a0.w = fmaf(v0.w, w0, a0.w);
            }
            float4 f = __ldg(feat4 + (size_t)node * 32 + lane);
            v.x = fmaf(eps1, f.x, a0.x + a1.x);
            v.y = fmaf(eps1, f.y, a0.y + a1.y);
            v.z = fmaf(eps1, f.z, a0.z + a1.z);
            v.w = fmaf(eps1, f.w, a0.w + a1.w);
        }
        // split 4 fp32 -> 2 u32 hi + 2 u32 lo; store 8B per tile per lane
        uint32_t h01, l01, h23, l23;
        split2(v.x, v.y, h01, l01);
        split2(v.z, v.w, h23, l23);
        uint32_t o = (uint32_t)r * LDB_B + (uint32_t)lane * 8;
        *(uint2*)(sm + SM_XHI + o) = make_uint2(h01, h23);
        *(uint2*)(sm + SM_XLO + o) = make_uint2(l01, l23);
    }

    float acc[8][4];
    #pragma unroll
    for (int t = 0; t < 8; t++)
        #pragma unroll
        for (int j = 0; j < 4; j++) acc[t][j] = 0.f;

    wait_cp_n<1>();          // W1h1 arrived
    __syncthreads();

    // ---- L1 half a (k 0..63) ----
    do_half(smb, SM_WS0, SM_WS1, 0, m0, wn, lane, acc);

    wait_cp_n<0>();          // W1h2 arrived
    __syncthreads();         // all warps done reading WS0/1
    stage_whalf(smb, SM_WS0, SM_WS1, wmat2, tid);   // W2h1 streams under L1b

    // ---- L1 half b (k 64..127) ----
    do_half(smb, SM_WS2, SM_WS3, 1, m0, wn, lane, acc);
    __syncthreads();         // all warps done reading X (and W1h2)

    // writeback h1 = leaky(acc + b1) into X tiles
    {
        const int r0 = m0 + (lane >> 2);
        const int c0 = 2 * (lane & 3);
        #pragma unroll
        for (int p = 0; p < 4; p++) {
            #pragma unroll
            for (int s = 0; s < 2; s++) {
                int c = (wn * 4 + p) * 16 + s * 8 + c0;
                float v0 = leaky(acc[2*p+s][0] + sB1[c]);
                float v1 = leaky(acc[2*p+s][1] + sB1[c + 1]);
                float v2 = leaky(acc[2*p+s][2] + sB1[c]);
                float v3 = leaky(acc[2*p+s][3] + sB1[c + 1]);
                uint32_t h01, l01, h23, l23;
                split2(v0, v1, h01, l01);
                split2(v2, v3, h23, l23);
                uint32_t o0 = (uint32_t)r0 * LDB_B + (uint32_t)c * 2;
                uint32_t o1 = o0 + 8u * LDB_B;
                *(uint32_t*)(sm + SM_XHI + o0) = h01;
                *(uint32_t*)(sm + SM_XLO + o0) = l01;
                *(uint32_t*)(sm + SM_XHI + o1) = h23;
                *(uint32_t*)(sm + SM_XLO + o1) = l23;
            }
        }
    }

    #pragma unroll
    for (int t = 0; t < 8; t++)
        #pragma unroll
        for (int j = 0; j < 4; j++) acc[t][j] = 0.f;

    wait_cp_n<0>();          // W2h1 arrived
    __syncthreads();         // h1 writeback visible; W2h1 visible
    stage_whalf(smb, SM_WS2, SM_WS3, wmat2 + 2 * WHALF_U4, tid);  // W2h2 under L2a

    // ---- L2 half a ----
    do_half(smb, SM_WS0, SM_WS1, 0, m0, wn, lane, acc);

    wait_cp_n<0>();          // W2h2 arrived
    __syncthreads();
    // ---- L2 half b ----
    do_half(smb, SM_WS2, SM_WS3, 1, m0, wn, lane, acc);

    // epilogue staging (reuses WS0/1; all warps past L2a reads)
    __syncthreads();
    {
        float* fst = (float*)(sm + SM_FST);
        const int r0 = m0 + (lane >> 2);
        const int c0 = 2 * (lane & 3);
        #pragma unroll
        for (int p = 0; p < 4; p++) {
            #pragma unroll
            for (int s = 0; s < 2; s++) {
                int c = (wn * 4 + p) * 16 + s * 8 + c0;
                float v0 = leaky(acc[2*p+s][0] + sB2[c]);
                float v1 = leaky(acc[2*p+s][1] + sB2[c + 1]);
                float v2 = leaky(acc[2*p+s][2] + sB2[c]);
                float v3 = leaky(acc[2*p+s][3] + sB2[c + 1]);
                *(float2*)(fst + (size_t)r0 * LDF + c)       = make_float2(v0, v1);
                *(float2*)(fst + (size_t)(r0 + 8) * LDF + c) = make_float2(v2, v3);
            }
        }
    }
    __syncthreads();

    // coalesced final writes: out = h2 + feat_self; h_out = h2
    {
        const float* fst = (const float*)(sm + SM_FST);
        #pragma unroll
        for (int i = 0; i < 8; i++) {
            int idx = tid + i * 256;
            int r = idx >> 5, c4 = idx & 31;
            int grow = row0 + r;
            if (grow >= N) continue;
            const float* p = fst + (size_t)r * LDF + c4 * 4;
            float4 h = make_float4(p[0], p[1], p[2], p[3]);
            float4 fv = __ldg(feat4 + (size_t)grow * 32 + c4);
            ((float4*)out)[(size_t)grow * 32 + c4] =
                make_float4(h.x + fv.x, h.y + fv.y, h.z + fv.z, h.w + fv.w);
            if (h_out)
                ((float4*)h_out)[(size_t)grow * 32 + c4] = h;
        }
    }
}

extern "C" void kernel_launch(void* const* d_in, const int* in_sizes, int n_in,
                              void* d_out, int out_size) {
    const float* feat_row = (const float*)d_in[0];
    const float* feat_col = (const float*)d_in[1];
    const int*   src_c2r  = (const int*)d_in[2];
    const int*   dst_c2r  = (const int*)d_in[3];
    const float* w_c2r    = (const float*)d_in[4];
    const int*   src_r2c  = (const int*)d_in[5];
    const int*   dst_r2c  = (const int*)d_in[6];
    const float* w_r2c    = (const float*)d_in[7];
    const float* W1_c2r   = (const float*)d_in[8];
    const float* b1_c2r   = (const float*)d_in[9];
    const float* W2_c2r   = (const float*)d_in[10];
    const float* b2_c2r   = (const float*)d_in[11];
    const float* W1_r2c   = (const float*)d_in[12];
    const float* b1_r2c   = (const float*)d_in[13];
    const float* W2_r2c   = (const float*)d_in[14];
    const float* b2_r2c   = (const float*)d_in[15];
    const float* eps_c2r  = (const float*)d_in[16];
    const float* eps_r2c  = (const float*)d_in[17];

    const int E = in_sizes[2];

    float* out_row = (float*)d_out;
    float* out_col = out_row + (size_t)NROW * D;

    float* hrow;
    uint4* wt;
    int *cnt, *ptr, *cur, *bsum;
    int2* edges;
    cudaGetSymbolAddress((void**)&hrow,  g_hrow);
    cudaGetSymbolAddress((void**)&wt,    g_wt);
    cudaGetSymbolAddress((void**)&cnt,   g_cnt);
    cudaGetSymbolAddress((void**)&ptr,   g_ptr);
    cudaGetSymbolAddress((void**)&cur,   g_cur);
    cudaGetSymbolAddress((void**)&bsum,  g_bsum);
    cudaGetSymbolAddress((void**)&edges, g_edges);

    const int MAT_U4 = 2 * 2 * WHALF_U4;
    const uint4* w1_a = wt + 0 * MAT_U4;
    const uint4* w2_a = wt + 1 * MAT_U4;
    const uint4* w1_b = wt + 2 * MAT_U4;
    const uint4* w2_b = wt + 3 * MAT_U4;

    cudaFuncSetAttribute(fused_kernel, cudaFuncAttributeMaxDynamicSharedMemorySize, SM_TOTAL);

    const int e2grid = (2 * E + 255) / 256;
    const int g_row = (NROW + BM - 1) / BM;
    const int g_col = (NCOL + BM - 1) / BM;
    const int nscan_blocks = (NTOT + 1023) / 1024;

    // ---- CSR build (both graphs jointly) ----
    zero_cnt_kernel<<<(NTOT + 255) / 256, 256>>>(cnt, NTOT);
    hist2_kernel<<<e2grid, 256>>>(dst_c2r, dst_r2c, cnt, E);
    scan_blk_kernel<<<nscan_blocks, 1024>>>(cnt, ptr, bsum, NTOT);
    scan_tot_kernel<<<1, 128>>>(bsum, nscan_blocks);
    scan_add_kernel<<<(NTOT + 255) / 256, 256>>>(ptr, cur, bsum, NTOT, 2 * E);
    scatter2_kernel<<<e2grid, 256>>>(src_c2r, dst_c2r, w_c2r, src_r2c, dst_r2c, w_r2c,
                                     cur, edges, E);
    split_w_kernel<<<32, 256>>>(W1_c2r, W2_c2r, W1_r2c, W2_r2c);

    // ---- col -> row (fused gather + MLP) ----
    fused_kernel<<<g_row, 256, SM_TOTAL>>>((const float4*)feat_col, feat_row, ptr, edges, 0,
                                           w1_a, w2_a, b1_c2r, b2_c2r, eps_c2r,
                                           hrow, out_row, NROW);
    // ---- row -> col (gathers from updated h_row) ----
    fused_kernel<<<g_col, 256, SM_TOTAL>>>((const float4*)hrow, feat_col, ptr, edges, NROW,
                                           w1_b, w2_b, b1_r2c, b2_r2c, eps_r2c,
                                           nullptr, out_col, NCOL);
}

// round 12
// speedup vs baseline: 1.0968x; 1.0968x over previous
#include <cuda_runtime.h>
#include <cuda_bf16.h>
#include <cstdint>

#define D      128
#define NROW   50000
#define NCOL   50000
#define NTOT   (NROW + NCOL)
#define BM     64

// X tile: 64 rows x 128 k bf16, row stride 272B
#define LDB_B   272
#define XTILE_B (64 * LDB_B)          // 17408
// W half-tile: 128 n-rows x 64 k bf16, row stride 144B
#define LDW_B   144
#define WHALF_B (128 * LDW_B)         // 18432
#define WHALF_U4 (WHALF_B / 16)       // 1152

// Scratch (alloc-free rule: __device__ globals)
__device__ float g_agg1[(size_t)NROW * D];
__device__ float g_agg2[(size_t)NCOL * D];
__device__ float g_hrow[(size_t)NROW * D];
__device__ uint4 g_wt[4][2][2][WHALF_U4];   // [matrix][khalf][hi/lo]
__device__ int   g_cnt[NTOT];
__device__ int   g_ptr[NTOT + 1];
__device__ int   g_cur[NTOT];
__device__ int   g_bsum[128];
__device__ int   g_flag;
__device__ int2  g_edges[1200000];

__device__ __forceinline__ float leaky(float v) { return v >= 0.f ? v : 0.01f * v; }

// ---------------- CSR build ----------------
__global__ void zero_cnt_kernel(int* __restrict__ cnt, int* __restrict__ flag, int n) {
    int i = blockIdx.x * blockDim.x + threadIdx.x;
    if (i < n) cnt[i] = 0;
    if (i == 0) *flag = 0;
}

__global__ void hist2_kernel(const int* __restrict__ dst1, const int* __restrict__ dst2,
                             int* __restrict__ cnt, int E) {
    int e = blockIdx.x * blockDim.x + threadIdx.x;
    if (e >= 2 * E) return;
    if (e < E) atomicAdd(cnt + __ldg(dst1 + e), 1);
    else       atomicAdd(cnt + NROW + __ldg(dst2 + e - E), 1);
}

// block-local exclusive scan + block totals; LAST block also scans the totals
// (folds the old scan_tot kernel in).
__global__ void scan_blk_kernel(const int* __restrict__ cnt, int* __restrict__ ptr,
                                int* __restrict__ bsum, int* __restrict__ flag, int n) {
    __shared__ int wsum[32];
    __shared__ int tmp[128];
    __shared__ int is_last;
    int tid = threadIdx.x, lane = tid & 31, wid = tid >> 5;
    int i = blockIdx.x * 1024 + tid;
    int x = (i < n) ? cnt[i] : 0;
    int v = x;
    #pragma unroll
    for (int o = 1; o < 32; o <<= 1) { int t = __shfl_up_sync(~0u, v, o); if (lane >= o) v += t; }
    if (lane == 31) wsum[wid] = v;
    __syncthreads();
    if (wid == 0) {
        int s = wsum[lane];
        #pragma unroll
        for (int o = 1; o < 32; o <<= 1) { int t = __shfl_up_sync(~0u, s, o); if (lane >= o) s += t; }
        wsum[lane] = s;
    }
    __syncthreads();
    int woff = wid ? wsum[wid - 1] : 0;
    if (i < n) ptr[i] = woff + v - x;

    // last-block pattern replaces scan_tot
    if (tid == 0) {
        bsum[blockIdx.x] = wsum[31];
        __threadfence();
        int old = atomicAdd(flag, 1);
        is_last = (old == (int)gridDim.x - 1) ? 1 : 0;
    }
    __syncthreads();
    if (is_last) {
        __threadfence();
        int nb = gridDim.x;                 // <= 128
        int xx = (tid < nb) ? bsum[tid] : 0;
        if (tid < 128) tmp[tid] = xx;
        __syncthreads();
        for (int o = 1; o < 128; o <<= 1) {
            int t = (tid >= o && tid < 128) ? tmp[tid - o] : 0;
            __syncthreads();
            if (tid < 128) tmp[tid] += t;
            __syncthreads();
        }
        if (tid < nb) bsum[tid] = tmp[tid] - xx;
    }
}

__global__ void scan_add_kernel(int* __restrict__ ptr, int* __restrict__ cur,
                                const int* __restrict__ bsum, int n, int total) {
    int i = blockIdx.x * blockDim.x + threadIdx.x;
    if (i < n) {
        int v = ptr[i] + bsum[i >> 10];
        ptr[i] = v;
        cur[i] = v;
    }
    if (i == 0) ptr[n] = total;
}

__global__ void scatter2_kernel(const int* __restrict__ src1, const int* __restrict__ dst1,
                                const float* __restrict__ w1,
                                const int* __restrict__ src2, const int* __restrict__ dst2,
                                const float* __restrict__ w2,
                                int* __restrict__ cur, int2* __restrict__ edges, int E) {
    int e = blockIdx.x * blockDim.x + threadIdx.x;
    if (e >= 2 * E) return;
    if (e < E) {
        int pos = atomicAdd(cur + __ldg(dst1 + e), 1);
        edges[pos] = make_int2(__ldg(src1 + e), __float_as_int(__ldg(w1 + e)));
    } else {
        int ee = e - E;
        int pos = atomicAdd(cur + NROW + __ldg(dst2 + ee), 1);
        edges[pos] = make_int2(__ldg(src2 + ee), __float_as_int(__ldg(w2 + ee)));
    }
}

// ---------------- CSR aggregation: one warp per dst node (R9 version) ----------------
__global__ void csr_agg_kernel(const float4* __restrict__ feat,
                               const int* __restrict__ ptr,
                               const int2* __restrict__ edges,
                               float* __restrict__ agg, int n, int off) {
    int t = blockIdx.x * blockDim.x + threadIdx.x;
    int node = t >> 5;
    if (node >= n) return;
    int lane = t & 31;
    int beg = __ldg(ptr + off + node);
    int end = __ldg(ptr + off + node + 1);
    float4 a0 = make_float4(0.f, 0.f, 0.f, 0.f);
    float4 a1 = make_float4(0.f, 0.f, 0.f, 0.f);
    int i = beg;
    for (; i + 2 <= end; i += 2) {
        int2 e0 = __ldg(edges + i);
        int2 e1 = __ldg(edges + i + 1);
        float w0 = __int_as_float(e0.y), w1 = __int_as_float(e1.y);
        float4 v0 = __ldg(feat + (size_t)e0.x * 32 + lane);
        float4 v1 = __ldg(feat + (size_t)e1.x * 32 + lane);
        a0.x = fmaf(v0.x, w0, a0.x); a0.y = fmaf(v0.y, w0, a0.y);
        a0.z = fmaf(v0.z, w0, a0.z); a0.w = fmaf(v0.w, w0, a0.w);
        a1.x = fmaf(v1.x, w1, a1.x); a1.y = fmaf(v1.y, w1, a1.y);
        a1.z = fmaf(v1.z, w1, a1.z); a1.w = fmaf(v1.w, w1, a1.w);
    }
    if (i < end) {
        int2 e0 = __ldg(edges + i);
        float w0 = __int_as_float(e0.y);
        float4 v0 = __ldg(feat + (size_t)e0.x * 32 + lane);
        a0.x = fmaf(v0.x, w0, a0.x); a0.y = fmaf(v0.y, w0, a0.y);
        a0.z = fmaf(v0.z, w0, a0.z); a0.w = fmaf(v0.w, w0, a0.w);
    }
    ((float4*)agg)[(size_t)node * 32 + lane] =
        make_float4(a0.x + a1.x, a0.y + a1.y, a0.z + a1.z, a0.w + a1.w);
}

// ---------------- weight pre-split ----------------
static __device__ __forceinline__ void split8(const float* x, uint32_t* hi, uint32_t* lo) {
    #pragma unroll
    for (int j = 0; j < 4; j++) {
        __nv_bfloat16 h0 = __float2bfloat16(x[2*j]);
        __nv_bfloat16 h1 = __float2bfloat16(x[2*j+1]);
        __nv_bfloat16 l0 = __float2bfloat16(x[2*j]   - __bfloat162float(h0));
        __nv_bfloat16 l1 = __float2bfloat16(x[2*j+1] - __bfloat162float(h1));
        hi[j] = (uint32_t)__bfloat16_as_ushort(h0) | ((uint32_t)__bfloat16_as_ushort(h1) << 16);
        lo[j] = (uint32_t)__bfloat16_as_ushort(l0) | ((uint32_t)__bfloat16_as_ushort(l1) << 16);
    }
}

static __device__ __forceinline__ void split2(float x0, float x1, uint32_t& hi, uint32_t& lo) {
    __nv_bfloat16 h0 = __float2bfloat16(x0);
    __nv_bfloat16 h1 = __float2bfloat16(x1);
    __nv_bfloat16 l0 = __float2bfloat16(x0 - __bfloat162float(h0));
    __nv_bfloat16 l1 = __float2bfloat16(x1 - __bfloat162float(h1));
    hi = (uint32_t)__bfloat16_as_ushort(h0) | ((uint32_t)__bfloat16_as_ushort(h1) << 16);
    lo = (uint32_t)__bfloat16_as_ushort(l0) | ((uint32_t)__bfloat16_as_ushort(l1) << 16);
}

__global__ void split_w_kernel(const float* __restrict__ Wa, const float* __restrict__ Wb,
                               const float* __restrict__ Wc, const float* __restrict__ Wd) {
    int task = blockIdx.x * blockDim.x + threadIdx.x;   // 0..8191
    int m = task >> 11;
    int tt = task & 2047;
    int n = tt & 127, kg = tt >> 7;
    const float* W = (m == 0) ? Wa : (m == 1) ? Wb : (m == 2) ? Wc : Wd;
    float v[8];
    #pragma unroll
    for (int j = 0; j < 8; j++) v[j] = __ldg(W + (kg * 8 + j) * D + n);
    uint32_t hi[4], lo[4];
    split8(v, hi, lo);
    int half = kg >> 3, kgl = kg & 7;
    int idx = n * 9 + kgl;
    g_wt[m][half][0][idx] = make_uint4(hi[0], hi[1], hi[2], hi[3]);
    g_wt[m][half][1][idx] = make_uint4(lo[0], lo[1], lo[2], lo[3]);
}

// ---------------- HMMA (mma.sync) MLP, pipelined W halves ----------------
#define SM_XHI  0
#define SM_XLO  (SM_XHI + XTILE_B)
#define SM_WS0  (SM_XLO + XTILE_B)
#define SM_WS1  (SM_WS0 + WHALF_B)
#define SM_WS2  (SM_WS1 + WHALF_B)
#define SM_WS3  (SM_WS2 + WHALF_B)
#define SM_B1   (SM_WS3 + WHALF_B)
#define SM_B2   (SM_B1 + 512)
#define SM_TOTAL (SM_B2 + 512)            // 109568 -> 2 CTAs/SM

static __device__ __forceinline__ uint32_t smem_u32(const void* p) {
    uint32_t a;
    asm("{ .reg .u64 t; cvta.to.shared.u64 t, %1; cvt.u32.u64 %0, t; }" : "=r"(a) : "l"(p));
    return a;
}

static __device__ __forceinline__ void ldsm4(uint32_t* r, uint32_t addr) {
    asm volatile("ldmatrix.sync.aligned.m8n8.x4.shared.b16 {%0,%1,%2,%3}, [%4];"
                 : "=r"(r[0]), "=r"(r[1]), "=r"(r[2]), "=r"(r[3]) : "r"(addr));
}

static __device__ __forceinline__ void mma16816(float* d, const uint32_t* a,
                                                uint32_t b0, uint32_t b1) {
    asm volatile("mma.sync.aligned.m16n8k16.row.col.f32.bf16.bf16.f32 "
                 "{%0,%1,%2,%3}, {%4,%5,%6,%7}, {%8,%9}, {%0,%1,%2,%3};"
                 : "+f"(d[0]), "+f"(d[1]), "+f"(d[2]), "+f"(d[3])
                 : "r"(a[0]), "r"(a[1]), "r"(a[2]), "r"(a[3]), "r"(b0), "r"(b1));
}

static __device__ __forceinline__ void stage_whalf(uint32_t smb, uint32_t hi_off, uint32_t lo_off,
                                                   const uint4* __restrict__ half_base, int tid) {
    const uint4* hi = half_base;
    const uint4* lo = half_base + WHALF_U4;
    for (int i = tid; i < WHALF_U4; i += 256) {
        asm volatile("cp.async.cg.shared.global [%0], [%1], 16;"
                     :: "r"(smb + hi_off + (uint32_t)i * 16), "l"(hi + i));
        asm volatile("cp.async.cg.shared.global [%0], [%1], 16;"
                     :: "r"(smb + lo_off + (uint32_t)i * 16), "l"(lo + i));
    }
    asm volatile("cp.async.commit_group;" ::: "memory");
}
template <int N>
static __device__ __forceinline__ void wait_cp_n() {
    asm volatile("cp.async.wait_group %0;" :: "n"(N) : "memory");
}

static __device__ __forceinline__ void do_half(uint32_t smb, uint32_t whi, uint32_t wlo,
                                               int khalf, int m0, int wn, int lane,
                                               float acc[8][4]) {
    const int rsel = lane & 15;
    const uint32_t koff = (uint32_t)((lane >> 4) << 4);
    #pragma unroll
    for (int kk = 0; kk < 4; kk++) {
        uint32_t rowkA = (uint32_t)(khalf * 4 + kk) * 32 + koff;
        uint32_t rowkB = (uint32_t)kk * 32 + koff;
        uint32_t ahi[4], alo[4];
        ldsm4(ahi, smb + SM_XHI + (uint32_t)(m0 + rsel) * LDB_B + rowkA);
        ldsm4(alo, smb + SM_XLO + (uint32_t)(m0 + rsel) * LDB_B + rowkA);
        #pragma unroll
        for (int p = 0; p < 4; p++) {
            uint32_t boff = (uint32_t)((wn * 4 + p) * 16 + rsel) * LDW_B + rowkB;
            uint32_t bh[4], bl[4];
            ldsm4(bh, smb + whi + boff);
            ldsm4(bl, smb + wlo + boff);
            mma16816(acc[2*p],   ahi, bh[0], bh[2]);
            mma16816(acc[2*p+1], ahi, bh[1], bh[3]);
            mma16816(acc[2*p],   ahi, bl[0], bl[2]);
            mma16816(acc[2*p+1], ahi, bl[1], bl[3]);
            mma16816(acc[2*p],   alo, bh[0], bh[2]);
            mma16816(acc[2*p+1], alo, bh[1], bh[3]);
        }
    }
}

__global__ void __launch_bounds__(256, 2)
mlp_tc_kernel(const float* __restrict__ feat, const float* __restrict__ agg,
              const uint4* __restrict__ wmat1, const uint4* __restrict__ wmat2,
              const float* __restrict__ b1, const float* __restrict__ b2,
              const float* __restrict__ eps_p,
              float* __restrict__ h_out, float* __restrict__ out, int N) {
    extern __shared__ char sm[];
    const uint32_t smb = smem_u32(sm);
    const int tid = threadIdx.x;
    const int wid = tid >> 5;
    const int lane = tid & 31;
    const int m0 = (wid & 3) * 16;
    const int wn = wid >> 2;
    const int row0 = blockIdx.x * BM;
    const float eps1 = 1.f + __ldg(eps_p);

    const float4* feat4 = (const float4*)feat;
    const float4* agg4  = (const float4*)agg;
    float* sB1 = (float*)(sm + SM_B1);
    float* sB2 = (float*)(sm + SM_B2);

    // prefetch W1 (both halves) under X staging
    stage_whalf(smb, SM_WS0, SM_WS1, wmat1, tid);                 // group: W1h1
    stage_whalf(smb, SM_WS2, SM_WS3, wmat1 + 2 * WHALF_U4, tid);  // group: W1h2

    if (tid < 128) {
        sB1[tid] = __ldg(b1 + tid);
        sB2[tid] = __ldg(b2 + tid);
    }

    // ---- stage x = (1+eps)*feat + agg as bf16 hi/lo (64 rows) ----
    #pragma unroll
    for (int i = 0; i < 4; i++) {
        int tt = tid + i * 256;
        int tr = tt >> 4, kg = tt & 15;
        int grow = row0 + tr;
        float v[8];
        if (grow < N) {
            float4 f0 = __ldg(feat4 + (size_t)grow * 32 + kg * 2);
            float4 f1 = __ldg(feat4 + (size_t)grow * 32 + kg * 2 + 1);
            float4 a0 = __ldg(agg4  + (size_t)grow * 32 + kg * 2);
            float4 a1 = __ldg(agg4  + (size_t)grow * 32 + kg * 2 + 1);
            v[0] = fmaf(eps1, f0.x, a0.x); v[1] = fmaf(eps1, f0.y, a0.y);
            v[2] = fmaf(eps1, f0.z, a0.z); v[3] = fmaf(eps1, f0.w, a0.w);
            v[4] = fmaf(eps1, f1.x, a1.x); v[5] = fmaf(eps1, f1.y, a1.y);
            v[6] = fmaf(eps1, f1.z, a1.z); v[7] = fmaf(eps1, f1.w, a1.w);
        } else {
            #pragma unroll
            for (int j = 0; j < 8; j++) v[j] = 0.f;
        }
        uint32_t hi[4], lo[4];
        split8(v, hi, lo);
        uint32_t off = (uint32_t)tr * LDB_B + (uint32_t)kg * 16;
        *(uint4*)(sm + SM_XHI + off) = make_uint4(hi[0], hi[1], hi[2], hi[3]);
        *(uint4*)(sm + SM_XLO + off) = make_uint4(lo[0], lo[1], lo[2], lo[3]);
    }

    float acc[8][4];
    #pragma unroll
    for (int t = 0; t < 8; t++)
        #pragma unroll
        for (int j = 0; j < 4; j++) acc[t][j] = 0.f;

    wait_cp_n<1>();          // W1h1 arrived
    __syncthreads();

    // ---- L1 half a (k 0..63) ----
    do_half(smb, SM_WS0, SM_WS1, 0, m0, wn, lane, acc);

    wait_cp_n<0>();          // W1h2 arrived
    __syncthreads();         // all warps done reading WS0/1
    stage_whalf(smb, SM_WS0, SM_WS1, wmat2, tid);   // W2h1 streams under L1b

    // ---- L1 half b (k 64..127) ----
    do_half(smb, SM_WS2, SM_WS3, 1, m0, wn, lane, acc);
    __syncthreads();         // all warps done reading X (and W1h2)

    // writeback h1 = leaky(acc + b1) into X tiles
    {
        const int r0 = m0 + (lane >> 2);
        const int c0 = 2 * (lane & 3);
        #pragma unroll
        for (int p = 0; p < 4; p++) {
            #pragma unroll
            for (int s = 0; s < 2; s++) {
                int c = (wn * 4 + p) * 16 + s * 8 + c0;
                float v0 = leaky(acc[2*p+s][0] + sB1[c]);
                float v1 = leaky(acc[2*p+s][1] + sB1[c + 1]);
                float v2 = leaky(acc[2*p+s][2] + sB1[c]);
                float v3 = leaky(acc[2*p+s][3] + sB1[c + 1]);
                uint32_t h01, l01, h23, l23;
                split2(v0, v1, h01, l01);
                split2(v2, v3, h23, l23);
                uint32_t o0 = (uint32_t)r0 * LDB_B + (uint32_t)c * 2;
                uint32_t o1 = o0 + 8u * LDB_B;
                *(uint32_t*)(sm + SM_XHI + o0) = h01;
                *(uint32_t*)(sm + SM_XLO + o0) = l01;
                *(uint32_t*)(sm + SM_XHI + o1) = h23;
                *(uint32_t*)(sm + SM_XLO + o1) = l23;
            }
        }
    }

    #pragma unroll
    for (int t = 0; t < 8; t++)
        #pragma unroll
        for (int j = 0; j < 4; j++) acc[t][j] = 0.f;

    wait_cp_n<0>();          // W2h1 arrived
    __syncthreads();         // h1 writeback visible; W2h1 visible
    stage_whalf(smb, SM_WS2, SM_WS3, wmat2 + 2 * WHALF_U4, tid);  // W2h2 under L2a

    // ---- L2 half a ----
    do_half(smb, SM_WS0, SM_WS1, 0, m0, wn, lane, acc);

    wait_cp_n<0>();          // W2h2 arrived
    __syncthreads();
    // ---- L2 half b ----
    do_half(smb, SM_WS2, SM_WS3, 1, m0, wn, lane, acc);

    // ---- direct epilogue: h2 = leaky(acc + b2); out = h2 + feat; h_out = h2 ----
    // (no smem staging, no barriers; lanes 0-3 etc. cover contiguous 32B sectors)
    {
        const int r0g = row0 + m0 + (lane >> 2);
        const int c0 = 2 * (lane & 3);
        #pragma unroll
        for (int p = 0; p < 4; p++) {
            #pragma unroll
            for (int s = 0; s < 2; s++) {
                int c = (wn * 4 + p) * 16 + s * 8 + c0;
                float v0 = leaky(acc[2*p+s][0] + sB2[c]);
                float v1 = leaky(acc[2*p+s][1] + sB2[c + 1]);
                float v2 = leaky(acc[2*p+s][2] + sB2[c]);
                float v3 = leaky(acc[2*p+s][3] + sB2[c + 1]);
                if (r0g < N) {
                    float2 f = *(const float2*)(feat + (size_t)r0g * D + c);
                    *(float2*)(out + (size_t)r0g * D + c) = make_float2(v0 + f.x, v1 + f.y);
                    if (h_out)
                        *(float2*)(h_out + (size_t)r0g * D + c) = make_float2(v0, v1);
                }
                if (r0g + 8 < N) {
                    float2 f = *(const float2*)(feat + (size_t)(r0g + 8) * D + c);
                    *(float2*)(out + (size_t)(r0g + 8) * D + c) = make_float2(v2 + f.x, v3 + f.y);
                    if (h_out)
                        *(float2*)(h_out + (size_t)(r0g + 8) * D + c) = make_float2(v2, v3);
                }
            }
        }
    }
}

extern "C" void kernel_launch(void* const* d_in, const int* in_sizes, int n_in,
                              void* d_out, int out_size) {
    const float* feat_row = (const float*)d_in[0];
    const float* feat_col = (const float*)d_in[1];
    const int*   src_c2r  = (const int*)d_in[2];
    const int*   dst_c2r  = (const int*)d_in[3];
    const float* w_c2r    = (const float*)d_in[4];
    const int*   src_r2c  = (const int*)d_in[5];
    const int*   dst_r2c  = (const int*)d_in[6];
    const float* w_r2c    = (const float*)d_in[7];
    const float* W1_c2r   = (const float*)d_in[8];
    const float* b1_c2r   = (const float*)d_in[9];
    const float* W2_c2r   = (const float*)d_in[10];
    const float* b2_c2r   = (const float*)d_in[11];
    const float* W1_r2c   = (const float*)d_in[12];
    const float* b1_r2c   = (const float*)d_in[13];
    const float* W2_r2c   = (const float*)d_in[14];
    const float* b2_r2c   = (const float*)d_in[15];
    const float* eps_c2r  = (const float*)d_in[16];
    const float* eps_r2c  = (const float*)d_in[17];

    const int E = in_sizes[2];

    float* out_row = (float*)d_out;
    float* out_col = out_row + (size_t)NROW * D;

    float *agg1, *agg2, *hrow;
    uint4* wt;
    int *cnt, *ptr, *cur, *bsum, *flag;
    int2* edges;
    cudaGetSymbolAddress((void**)&agg1,  g_agg1);
    cudaGetSymbolAddress((void**)&agg2,  g_agg2);
    cudaGetSymbolAddress((void**)&hrow,  g_hrow);
    cudaGetSymbolAddress((void**)&wt,    g_wt);
    cudaGetSymbolAddress((void**)&cnt,   g_cnt);
    cudaGetSymbolAddress((void**)&ptr,   g_ptr);
    cudaGetSymbolAddress((void**)&cur,   g_cur);
    cudaGetSymbolAddress((void**)&bsum,  g_bsum);
    cudaGetSymbolAddress((void**)&flag,  g_flag);
    cudaGetSymbolAddress((void**)&edges, g_edges);

    const int MAT_U4 = 2 * 2 * WHALF_U4;
    const uint4* w1_a = wt + 0 * MAT_U4;
    const uint4* w2_a = wt + 1 * MAT_U4;
    const uint4* w1_b = wt + 2 * MAT_U4;
    const uint4* w2_b = wt + 3 * MAT_U4;

    cudaFuncSetAttribute(mlp_tc_kernel, cudaFuncAttributeMaxDynamicSharedMemorySize, SM_TOTAL);

    const int e2grid = (2 * E + 255) / 256;
    const int g_row = (NROW + BM - 1) / BM;
    const int g_col = (NCOL + BM - 1) / BM;
    const int nscan_blocks = (NTOT + 1023) / 1024;
    const int agg_grid = (NROW * 32 + 255) / 256;

    // ---- CSR build (both graphs jointly) ----
    zero_cnt_kernel<<<(NTOT + 255) / 256, 256>>>(cnt, flag, NTOT);
    hist2_kernel<<<e2grid, 256>>>(dst_c2r, dst_r2c, cnt, E);
    scan_blk_kernel<<<nscan_blocks, 1024>>>(cnt, ptr, bsum, flag, NTOT);
    scan_add_kernel<<<(NTOT + 255) / 256, 256>>>(ptr, cur, bsum, NTOT, 2 * E);
    scatter2_kernel<<<e2grid, 256>>>(src_c2r, dst_c2r, w_c2r, src_r2c, dst_r2c, w_r2c,
                                     cur, edges, E);
    split_w_kernel<<<32, 256>>>(W1_c2r, W2_c2r, W1_r2c, W2_r2c);

    // ---- col -> row ----
    csr_agg_kernel<<<agg_grid, 256>>>((const float4*)feat_col, ptr, edges, agg1, NROW, 0);
    mlp_tc_kernel<<<g_row, 256, SM_TOTAL>>>(feat_row, agg1, w1_a, w2_a,
                                            b1_c2r, b2_c2r, eps_c2r, hrow, out_row, NROW);
    // ---- row -> col (uses updated h_row) ----
    csr_agg_kernel<<<agg_grid, 256>>>((const float4*)hrow, ptr, edges, agg2, NCOL, NROW);
    mlp_tc_kernel<<<g_col, 256, SM_TOTAL>>>(feat_col, agg2, w1_b, w2_b,
                                            b1_r2c, b2_r2c, eps_r2c, nullptr, out_col, NCOL);
}

// round 13
// speedup vs baseline: 1.1794x; 1.0753x over previous
#include <cuda_runtime.h>
#include <cuda_bf16.h>
#include <cstdint>

#define D      128
#define NROW   50000
#define NCOL   50000
#define NTOT   (NROW + NCOL)
#define BM     64

// X tile: 64 rows x 128 k bf16, row stride 272B
#define LDB_B   272
#define XTILE_B (64 * LDB_B)          // 17408
// W half-tile: 128 n-rows x 64 k bf16, row stride 144B
#define LDW_B   144
#define WHALF_B (128 * LDW_B)         // 18432
#define WHALF_U4 (WHALF_B / 16)       // 1152

// Scratch (alloc-free rule: __device__ globals)
__device__ float g_agg1[(size_t)NROW * D];
__device__ float g_agg2[(size_t)NCOL * D];
__device__ float g_hrow[(size_t)NROW * D];
__device__ uint4 g_wt[4][2][2][WHALF_U4];   // [matrix][khalf][hi/lo]
__device__ int   g_cnt[NTOT];
__device__ int   g_ptr[NTOT + 1];
__device__ int   g_cur[NTOT];
__device__ int   g_bsum[128];
__device__ int   g_flag;
__device__ int2  g_edges[1200000];

__device__ __forceinline__ float leaky(float v) { return v >= 0.f ? v : 0.01f * v; }

// ---------------- weight pre-split + counter zero (merged prep) ----------------
static __device__ __forceinline__ void split8(const float* x, uint32_t* hi, uint32_t* lo) {
    #pragma unroll
    for (int j = 0; j < 4; j++) {
        __nv_bfloat16 h0 = __float2bfloat16(x[2*j]);
        __nv_bfloat16 h1 = __float2bfloat16(x[2*j+1]);
        __nv_bfloat16 l0 = __float2bfloat16(x[2*j]   - __bfloat162float(h0));
        __nv_bfloat16 l1 = __float2bfloat16(x[2*j+1] - __bfloat162float(h1));
        hi[j] = (uint32_t)__bfloat16_as_ushort(h0) | ((uint32_t)__bfloat16_as_ushort(h1) << 16);
        lo[j] = (uint32_t)__bfloat16_as_ushort(l0) | ((uint32_t)__bfloat16_as_ushort(l1) << 16);
    }
}

static __device__ __forceinline__ void split2(float x0, float x1, uint32_t& hi, uint32_t& lo) {
    __nv_bfloat16 h0 = __float2bfloat16(x0);
    __nv_bfloat16 h1 = __float2bfloat16(x1);
    __nv_bfloat16 l0 = __float2bfloat16(x0 - __bfloat162float(h0));
    __nv_bfloat16 l1 = __float2bfloat16(x1 - __bfloat162float(h1));
    hi = (uint32_t)__bfloat16_as_ushort(h0) | ((uint32_t)__bfloat16_as_ushort(h1) << 16);
    lo = (uint32_t)__bfloat16_as_ushort(l0) | ((uint32_t)__bfloat16_as_ushort(l1) << 16);
}

__global__ void prep_kernel(const float* __restrict__ Wa, const float* __restrict__ Wb,
                            const float* __restrict__ Wc, const float* __restrict__ Wd,
                            int* __restrict__ cnt, int* __restrict__ flag) {
    int task = blockIdx.x * blockDim.x + threadIdx.x;   // 0..8191
    // zero counters (strided) + flag
    for (int i = task; i < NTOT; i += 8192) cnt[i] = 0;
    if (task == 0) *flag = 0;
    // weight split
    int m = task >> 11;
    int tt = task & 2047;
    int n = tt & 127, kg = tt >> 7;
    const float* W = (m == 0) ? Wa : (m == 1) ? Wb : (m == 2) ? Wc : Wd;
    float v[8];
    #pragma unroll
    for (int j = 0; j < 8; j++) v[j] = __ldg(W + (kg * 8 + j) * D + n);
    uint32_t hi[4], lo[4];
    split8(v, hi, lo);
    int half = kg >> 3, kgl = kg & 7;
    int idx = n * 9 + kgl;
    g_wt[m][half][0][idx] = make_uint4(hi[0], hi[1], hi[2], hi[3]);
    g_wt[m][half][1][idx] = make_uint4(lo[0], lo[1], lo[2], lo[3]);
}

// ---------------- CSR build ----------------
__global__ void hist2_kernel(const int* __restrict__ dst1, const int* __restrict__ dst2,
                             int* __restrict__ cnt, int E) {
    int e = blockIdx.x * blockDim.x + threadIdx.x;
    if (e >= 2 * E) return;
    if (e < E) atomicAdd(cnt + __ldg(dst1 + e), 1);
    else       atomicAdd(cnt + NROW + __ldg(dst2 + e - E), 1);
}

// block-local exclusive scan + block totals; LAST block also scans the totals.
__global__ void scan_blk_kernel(const int* __restrict__ cnt, int* __restrict__ ptr,
                                int* __restrict__ bsum, int* __restrict__ flag, int n) {
    __shared__ int wsum[32];
    __shared__ int tmp[128];
    __shared__ int is_last;
    int tid = threadIdx.x, lane = tid & 31, wid = tid >> 5;
    int i = blockIdx.x * 1024 + tid;
    int x = (i < n) ? cnt[i] : 0;
    int v = x;
    #pragma unroll
    for (int o = 1; o < 32; o <<= 1) { int t = __shfl_up_sync(~0u, v, o); if (lane >= o) v += t; }
    if (lane == 31) wsum[wid] = v;
    __syncthreads();
    if (wid == 0) {
        int s = wsum[lane];
        #pragma unroll
        for (int o = 1; o < 32; o <<= 1) { int t = __shfl_up_sync(~0u, s, o); if (lane >= o) s += t; }
        wsum[lane] = s;
    }
    __syncthreads();
    int woff = wid ? wsum[wid - 1] : 0;
    if (i < n) ptr[i] = woff + v - x;

    if (tid == 0) {
        bsum[blockIdx.x] = wsum[31];
        __threadfence();
        int old = atomicAdd(flag, 1);
        is_last = (old == (int)gridDim.x - 1) ? 1 : 0;
    }
    __syncthreads();
    if (is_last) {
        __threadfence();
        int nb = gridDim.x;                 // <= 128
        int xx = (tid < nb) ? bsum[tid] : 0;
        if (tid < 128) tmp[tid] = xx;
        __syncthreads();
        for (int o = 1; o < 128; o <<= 1) {
            int t = (tid >= o && tid < 128) ? tmp[tid - o] : 0;
            __syncthreads();
            if (tid < 128) tmp[tid] += t;
            __syncthreads();
        }
        if (tid < nb) bsum[tid] = tmp[tid] - xx;
    }
}

__global__ void scan_add_kernel(int* __restrict__ ptr, int* __restrict__ cur,
                                const int* __restrict__ bsum, int n, int total) {
    int i = blockIdx.x * blockDim.x + threadIdx.x;
    if (i < n) {
        int v = ptr[i] + bsum[i >> 10];
        ptr[i] = v;
        cur[i] = v;
    }
    if (i == 0) ptr[n] = total;
}

__global__ void scatter2_kernel(const int* __restrict__ src1, const int* __restrict__ dst1,
                                const float* __restrict__ w1,
                                const int* __restrict__ src2, const int* __restrict__ dst2,
                                const float* __restrict__ w2,
                                int* __restrict__ cur, int2* __restrict__ edges, int E) {
    int e = blockIdx.x * blockDim.x + threadIdx.x;
    if (e >= 2 * E) return;
    if (e < E) {
        int pos = atomicAdd(cur + __ldg(dst1 + e), 1);
        edges[pos] = make_int2(__ldg(src1 + e), __float_as_int(__ldg(w1 + e)));
    } else {
        int ee = e - E;
        int pos = atomicAdd(cur + NROW + __ldg(dst2 + ee), 1);
        edges[pos] = make_int2(__ldg(src2 + ee), __float_as_int(__ldg(w2 + ee)));
    }
}

// ---------------- CSR aggregation: one warp per dst node (R9 version) ----------------
__global__ void csr_agg_kernel(const float4* __restrict__ feat,
                               const int* __restrict__ ptr,
                               const int2* __restrict__ edges,
                               float* __restrict__ agg, int n, int off) {
    int t = blockIdx.x * blockDim.x + threadIdx.x;
    int node = t >> 5;
    if (node >= n) return;
    int lane = t & 31;
    int beg = __ldg(ptr + off + node);
    int end = __ldg(ptr + off + node + 1);
    float4 a0 = make_float4(0.f, 0.f, 0.f, 0.f);
    float4 a1 = make_float4(0.f, 0.f, 0.f, 0.f);
    int i = beg;
    for (; i + 2 <= end; i += 2) {
        int2 e0 = __ldg(edges + i);
        int2 e1 = __ldg(edges + i + 1);
        float w0 = __int_as_float(e0.y), w1 = __int_as_float(e1.y);
        float4 v0 = __ldg(feat + (size_t)e0.x * 32 + lane);
        float4 v1 = __ldg(feat + (size_t)e1.x * 32 + lane);
        a0.x = fmaf(v0.x, w0, a0.x); a0.y = fmaf(v0.y, w0, a0.y);
        a0.z = fmaf(v0.z, w0, a0.z); a0.w = fmaf(v0.w, w0, a0.w);
        a1.x = fmaf(v1.x, w1, a1.x); a1.y = fmaf(v1.y, w1, a1.y);
        a1.z = fmaf(v1.z, w1, a1.z); a1.w = fmaf(v1.w, w1, a1.w);
    }
    if (i < end) {
        int2 e0 = __ldg(edges + i);
        float w0 = __int_as_float(e0.y);
        float4 v0 = __ldg(feat + (size_t)e0.x * 32 + lane);
        a0.x = fmaf(v0.x, w0, a0.x); a0.y = fmaf(v0.y, w0, a0.y);
        a0.z = fmaf(v0.z, w0, a0.z); a0.w = fmaf(v0.w, w0, a0.w);
    }
    ((float4*)agg)[(size_t)node * 32 + lane] =
        make_float4(a0.x + a1.x, a0.y + a1.y, a0.z + a1.z, a0.w + a1.w);
}

// ---------------- HMMA (mma.sync) MLP, pipelined W halves ----------------
#define SM_XHI  0
#define SM_XLO  (SM_XHI + XTILE_B)
#define SM_WS0  (SM_XLO + XTILE_B)
#define SM_WS1  (SM_WS0 + WHALF_B)
#define SM_WS2  (SM_WS1 + WHALF_B)
#define SM_WS3  (SM_WS2 + WHALF_B)
#define SM_B1   (SM_WS3 + WHALF_B)
#define SM_B2   (SM_B1 + 512)
#define SM_TOTAL (SM_B2 + 512)            // 109568 -> 2 CTAs/SM
#define SM_FST  SM_WS0                    // epilogue fp32 staging (64*132*4=33792 <= 2 slots)
#define LDF     132

static __device__ __forceinline__ uint32_t smem_u32(const void* p) {
    uint32_t a;
    asm("{ .reg .u64 t; cvta.to.shared.u64 t, %1; cvt.u32.u64 %0, t; }" : "=r"(a) : "l"(p));
    return a;
}

static __device__ __forceinline__ void ldsm4(uint32_t* r, uint32_t addr) {
    asm volatile("ldmatrix.sync.aligned.m8n8.x4.shared.b16 {%0,%1,%2,%3}, [%4];"
                 : "=r"(r[0]), "=r"(r[1]), "=r"(r[2]), "=r"(r[3]) : "r"(addr));
}

static __device__ __forceinline__ void mma16816(float* d, const uint32_t* a,
                                                uint32_t b0, uint32_t b1) {
    asm volatile("mma.sync.aligned.m16n8k16.row.col.f32.bf16.bf16.f32 "
                 "{%0,%1,%2,%3}, {%4,%5,%6,%7}, {%8,%9}, {%0,%1,%2,%3};"
                 : "+f"(d[0]), "+f"(d[1]), "+f"(d[2]), "+f"(d[3])
                 : "r"(a[0]), "r"(a[1]), "r"(a[2]), "r"(a[3]), "r"(b0), "r"(b1));
}

static __device__ __forceinline__ void stage_whalf(uint32_t smb, uint32_t hi_off, uint32_t lo_off,
                                                   const uint4* __restrict__ half_base, int tid) {
    const uint4* hi = half_base;
    const uint4* lo = half_base + WHALF_U4;
    for (int i = tid; i < WHALF_U4; i += 256) {
        asm volatile("cp.async.cg.shared.global [%0], [%1], 16;"
                     :: "r"(smb + hi_off + (uint32_t)i * 16), "l"(hi + i));
        asm volatile("cp.async.cg.shared.global [%0], [%1], 16;"
                     :: "r"(smb + lo_off + (uint32_t)i * 16), "l"(lo + i));
    }
    asm volatile("cp.async.commit_group;" ::: "memory");
}
template <int N>
static __device__ __forceinline__ void wait_cp_n() {
    asm volatile("cp.async.wait_group %0;" :: "n"(N) : "memory");
}

// one k-half of a layer, 2x4 warp grid: warp owns rows [mg*32, +32), cols [ng*32, +32).
// acc layout: acc[mt*4 + nb*2 + s][4], mt in {0,1} (16-row tile), nb in {0,1} (16-n tile),
// s in {0,1} (8-n fragment).
static __device__ __forceinline__ void do_half(uint32_t smb, uint32_t whi, uint32_t wlo,
                                               int khalf, int mg, int ng, int lane,
                                               float acc[8][4]) {
    const int rsel = lane & 15;
    const uint32_t koff = (uint32_t)((lane >> 4) << 4);
    #pragma unroll
    for (int kk = 0; kk < 4; kk++) {
        uint32_t rowkA = (uint32_t)(khalf * 4 + kk) * 32 + koff;
        uint32_t rowkB = (uint32_t)kk * 32 + koff;
        // B fragments: 2 x 16-n groups (hi+lo)
        uint32_t bh[2][4], bl[2][4];
        #pragma unroll
        for (int nb = 0; nb < 2; nb++) {
            uint32_t boff = (uint32_t)(ng * 32 + nb * 16 + rsel) * LDW_B + rowkB;
            ldsm4(bh[nb], smb + whi + boff);
            ldsm4(bl[nb], smb + wlo + boff);
        }
        #pragma unroll
        for (int mt = 0; mt < 2; mt++) {
            uint32_t aoff = (uint32_t)(mg * 32 + mt * 16 + rsel) * LDB_B + rowkA;
            uint32_t ahi[4], alo[4];
            ldsm4(ahi, smb + SM_XHI + aoff);
            ldsm4(alo, smb + SM_XLO + aoff);
            #pragma unroll
            for (int nb = 0; nb < 2; nb++) {
                float* d0 = acc[mt * 4 + nb * 2];
                float* d1 = acc[mt * 4 + nb * 2 + 1];
                mma16816(d0, ahi, bh[nb][0], bh[nb][2]);
                mma16816(d1, ahi, bh[nb][1], bh[nb][3]);
                mma16816(d0, ahi, bl[nb][0], bl[nb][2]);
                mma16816(d1, ahi, bl[nb][1], bl[nb][3]);
                mma16816(d0, alo, bh[nb][0], bh[nb][2]);
                mma16816(d1, alo, bh[nb][1], bh[nb][3]);
            }
        }
    }
}

__global__ void __launch_bounds__(256, 2)
mlp_tc_kernel(const float* __restrict__ feat, const float* __restrict__ agg,
              const uint4* __restrict__ wmat1, const uint4* __restrict__ wmat2,
              const float* __restrict__ b1, const float* __restrict__ b2,
              const float* __restrict__ eps_p,
              float* __restrict__ h_out, float* __restrict__ out, int N) {
    extern __shared__ char sm[];
    const uint32_t smb = smem_u32(sm);
    const int tid = threadIdx.x;
    const int wid = tid >> 5;
    const int lane = tid & 31;
    const int mg = wid & 1;            // 2 m-groups of 32 rows
    const int ng = wid >> 1;           // 4 n-groups of 32 cols
    const int row0 = blockIdx.x * BM;
    const float eps1 = 1.f + __ldg(eps_p);

    const float4* feat4 = (const float4*)feat;
    const float4* agg4  = (const float4*)agg;
    float* sB1 = (float*)(sm + SM_B1);
    float* sB2 = (float*)(sm + SM_B2);

    // prefetch W1 (both halves) under X staging
    stage_whalf(smb, SM_WS0, SM_WS1, wmat1, tid);                 // group: W1h1
    stage_whalf(smb, SM_WS2, SM_WS3, wmat1 + 2 * WHALF_U4, tid);  // group: W1h2

    if (tid < 128) {
        sB1[tid] = __ldg(b1 + tid);
        sB2[tid] = __ldg(b2 + tid);
    }

    // ---- stage x = (1+eps)*feat + agg as bf16 hi/lo (64 rows) ----
    #pragma unroll
    for (int i = 0; i < 4; i++) {
        int tt = tid + i * 256;
        int tr = tt >> 4, kg = tt & 15;
        int grow = row0 + tr;
        float v[8];
        if (grow < N) {
            float4 f0 = __ldg(feat4 + (size_t)grow * 32 + kg * 2);
            float4 f1 = __ldg(feat4 + (size_t)grow * 32 + kg * 2 + 1);
            float4 a0 = __ldg(agg4  + (size_t)grow * 32 + kg * 2);
            float4 a1 = __ldg(agg4  + (size_t)grow * 32 + kg * 2 + 1);
            v[0] = fmaf(eps1, f0.x, a0.x); v[1] = fmaf(eps1, f0.y, a0.y);
            v[2] = fmaf(eps1, f0.z, a0.z); v[3] = fmaf(eps1, f0.w, a0.w);
            v[4] = fmaf(eps1, f1.x, a1.x); v[5] = fmaf(eps1, f1.y, a1.y);
            v[6] = fmaf(eps1, f1.z, a1.z); v[7] = fmaf(eps1, f1.w, a1.w);
        } else {
            #pragma unroll
            for (int j = 0; j < 8; j++) v[j] = 0.f;
        }
        uint32_t hi[4], lo[4];
        split8(v, hi, lo);
        uint32_t off = (uint32_t)tr * LDB_B + (uint32_t)kg * 16;
        *(uint4*)(sm + SM_XHI + off) = make_uint4(hi[0], hi[1], hi[2], hi[3]);
        *(uint4*)(sm + SM_XLO + off) = make_uint4(lo[0], lo[1], lo[2], lo[3]);
    }

    float acc[8][4];
    #pragma unroll
    for (int t = 0; t < 8; t++)
        #pragma unroll
        for (int j = 0; j < 4; j++) acc[t][j] = 0.f;

    wait_cp_n<1>();          // W1h1 arrived
    __syncthreads();

    // ---- L1 half a (k 0..63) ----
    do_half(smb, SM_WS0, SM_WS1, 0, mg, ng, lane, acc);

    wait_cp_n<0>();          // W1h2 arrived
    __syncthreads();         // all warps done reading WS0/1
    stage_whalf(smb, SM_WS0, SM_WS1, wmat2, tid);   // W2h1 streams under L1b

    // ---- L1 half b (k 64..127) ----
    do_half(smb, SM_WS2, SM_WS3, 1, mg, ng, lane, acc);
    __syncthreads();         // all warps done reading X (and W1h2)

    // writeback h1 = leaky(acc + b1) into X tiles
    {
        const int c0 = 2 * (lane & 3);
        #pragma unroll
        for (int mt = 0; mt < 2; mt++) {
            const int r0 = mg * 32 + mt * 16 + (lane >> 2);
            #pragma unroll
            for (int nb = 0; nb < 2; nb++) {
                #pragma unroll
                for (int s = 0; s < 2; s++) {
                    int c = ng * 32 + nb * 16 + s * 8 + c0;
                    const float* a = acc[mt * 4 + nb * 2 + s];
                    float v0 = leaky(a[0] + sB1[c]);
                    float v1 = leaky(a[1] + sB1[c + 1]);
                    float v2 = leaky(a[2] + sB1[c]);
                    float v3 = leaky(a[3] + sB1[c + 1]);
                    uint32_t h01, l01, h23, l23;
                    split2(v0, v1, h01, l01);
                    split2(v2, v3, h23, l23);
                    uint32_t o0 = (uint32_t)r0 * LDB_B + (uint32_t)c * 2;
                    uint32_t o1 = o0 + 8u * LDB_B;
                    *(uint32_t*)(sm + SM_XHI + o0) = h01;
                    *(uint32_t*)(sm + SM_XLO + o0) = l01;
                    *(uint32_t*)(sm + SM_XHI + o1) = h23;
                    *(uint32_t*)(sm + SM_XLO + o1) = l23;
                }
            }
        }
    }

    #pragma unroll
    for (int t = 0; t < 8; t++)
        #pragma unroll
        for (int j = 0; j < 4; j++) acc[t][j] = 0.f;

    wait_cp_n<0>();          // W2h1 arrived
    __syncthreads();         // h1 writeback visible; W2h1 visible
    stage_whalf(smb, SM_WS2, SM_WS3, wmat2 + 2 * WHALF_U4, tid);  // W2h2 under L2a

    // ---- L2 half a ----
    do_half(smb, SM_WS0, SM_WS1, 0, mg, ng, lane, acc);

    wait_cp_n<0>();          // W2h2 arrived
    __syncthreads();
    // ---- L2 half b ----
    do_half(smb, SM_WS2, SM_WS3, 1, mg, ng, lane, acc);

    // epilogue staging (reuses WS0/1; all warps past L2a reads)
    __syncthreads();
    {
        float* fst = (float*)(sm + SM_FST);
        const int c0 = 2 * (lane & 3);
        #pragma unroll
        for (int mt = 0; mt < 2; mt++) {
            const int r0 = mg * 32 + mt * 16 + (lane >> 2);
            #pragma unroll
            for (int nb = 0; nb < 2; nb++) {
                #pragma unroll
                for (int s = 0; s < 2; s++) {
                    int c = ng * 32 + nb * 16 + s * 8 + c0;
                    const float* a = acc[mt * 4 + nb * 2 + s];
                    float v0 = leaky(a[0] + sB2[c]);
                    float v1 = leaky(a[1] + sB2[c + 1]);
                    float v2 = leaky(a[2] + sB2[c]);
                    float v3 = leaky(a[3] + sB2[c + 1]);
                    *(float2*)(fst + (size_t)r0 * LDF + c)       = make_float2(v0, v1);
                    *(float2*)(fst + (size_t)(r0 + 8) * LDF + c) = make_float2(v2, v3);
                }
            }
        }
    }
    __syncthreads();

    // coalesced final writes: out = h2 + feat; h_out = h2
    {
        const float* fst = (const float*)(sm + SM_FST);
        #pragma unroll
        for (int i = 0; i < 8; i++) {
            int idx = tid + i * 256;
            int r = idx >> 5, c4 = idx & 31;
            int grow = row0 + r;
            if (grow >= N) continue;
            const float* p = fst + (size_t)r * LDF + c4 * 4;
            float4 h = make_float4(p[0], p[1], p[2], p[3]);
            float4 fv = __ldg(feat4 + (size_t)grow * 32 + c4);
            ((float4*)out)[(size_t)grow * 32 + c4] =
                make_float4(h.x + fv.x, h.y + fv.y, h.z + fv.z, h.w + fv.w);
            if (h_out)
                ((float4*)h_out)[(size_t)grow * 32 + c4] = h;
        }
    }
}

extern "C" void kernel_launch(void* const* d_in, const int* in_sizes, int n_in,
                              void* d_out, int out_size) {
    const float* feat_row = (const float*)d_in[0];
    const float* feat_col = (const float*)d_in[1];
    const int*   src_c2r  = (const int*)d_in[2];
    const int*   dst_c2r  = (const int*)d_in[3];
    const float* w_c2r    = (const float*)d_in[4];
    const int*   src_r2c  = (const int*)d_in[5];
    const int*   dst_r2c  = (const int*)d_in[6];
    const float* w_r2c    = (const float*)d_in[7];
    const float* W1_c2r   = (const float*)d_in[8];
    const float* b1_c2r   = (const float*)d_in[9];
    const float* W2_c2r   = (const float*)d_in[10];
    const float* b2_c2r   = (const float*)d_in[11];
    const float* W1_r2c   = (const float*)d_in[12];
    const float* b1_r2c   = (const float*)d_in[13];
    const float* W2_r2c   = (const float*)d_in[14];
    const float* b2_r2c   = (const float*)d_in[15];
    const float* eps_c2r  = (const float*)d_in[16];
    const float* eps_r2c  = (const float*)d_in[17];

    const int E = in_sizes[2];

    float* out_row = (float*)d_out;
    float* out_col = out_row + (size_t)NROW * D;

    float *agg1, *agg2, *hrow;
    uint4* wt;
    int *cnt, *ptr, *cur, *bsum, *flag;
    int2* edges;
    cudaGetSymbolAddress((void**)&agg1,  g_agg1);
    cudaGetSymbolAddress((void**)&agg2,  g_agg2);
    cudaGetSymbolAddress((void**)&hrow,  g_hrow);
    cudaGetSymbolAddress((void**)&wt,    g_wt);
    cudaGetSymbolAddress((void**)&cnt,   g_cnt);
    cudaGetSymbolAddress((void**)&ptr,   g_ptr);
    cudaGetSymbolAddress((void**)&cur,   g_cur);
    cudaGetSymbolAddress((void**)&bsum,  g_bsum);
    cudaGetSymbolAddress((void**)&flag,  g_flag);
    cudaGetSymbolAddress((void**)&edges, g_edges);

    const int MAT_U4 = 2 * 2 * WHALF_U4;
    const uint4* w1_a = wt + 0 * MAT_U4;
    const uint4* w2_a = wt + 1 * MAT_U4;
    const uint4* w1_b = wt + 2 * MAT_U4;
    const uint4* w2_b = wt + 3 * MAT_U4;

    cudaFuncSetAttribute(mlp_tc_kernel, cudaFuncAttributeMaxDynamicSharedMemorySize, SM_TOTAL);

    const int e2grid = (2 * E + 255) / 256;
    const int g_row = (NROW + BM - 1) / BM;
    const int g_col = (NCOL + BM - 1) / BM;
    const int nscan_blocks = (NTOT + 1023) / 1024;
    const int agg_grid = (NROW * 32 + 255) / 256;

    // ---- CSR build (5 launches) ----
    prep_kernel<<<32, 256>>>(W1_c2r, W2_c2r, W1_r2c, W2_r2c, cnt, flag);
    hist2_kernel<<<e2grid, 256>>>(dst_c2r, dst_r2c, cnt, E);
    scan_blk_kernel<<<nscan_blocks, 1024>>>(cnt, ptr, bsum, flag, NTOT);
    scan_add_kernel<<<(NTOT + 255) / 256, 256>>>(ptr, cur, bsum, NTOT, 2 * E);
    scatter2_kernel<<<e2grid, 256>>>(src_c2r, dst_c2r, w_c2r, src_r2c, dst_r2c, w_r2c,
                                     cur, edges, E);

    // ---- col -> row ----
    csr_agg_kernel<<<agg_grid, 256>>>((const float4*)feat_col, ptr, edges, agg1, NROW, 0);
    mlp_tc_kernel<<<g_row, 256, SM_TOTAL>>>(feat_row, agg1, w1_a, w2_a,
                                            b1_c2r, b2_c2r, eps_c2r, hrow, out_row, NROW);
    // ---- row -> col (uses updated h_row) ----
    csr_agg_kernel<<<agg_grid, 256>>>((const float4*)hrow, ptr, edges, agg2, NCOL, NROW);
    mlp_tc_kernel<<<g_col, 256, SM_TOTAL>>>(feat_col, agg2, w1_b, w2_b,
                                            b1_r2c, b2_r2c, eps_r2c, nullptr, out_col, NCOL);
}